// round 1
// baseline (speedup 1.0000x reference)
#include <cuda_runtime.h>
#include <cuda_bf16.h>
#include <math.h>

// Problem constants
#define NP 64
#define NR 8
#define NK 500
#define H_DIM 256
#define HEADS 8
#define HD 32
#define VD 8
#define B_DIM (NP*NR)          // 512
#define GATES_N (4*H_DIM)      // 1024

#define NEG_INF (__int_as_float(0xff800000))

// ---------------- scratch (no allocation allowed) ----------------
__device__ float g_gates[B_DIM * GATES_N];   // 512x1024
__device__ float g_xg[B_DIM * H_DIM];        // glimpse output (pre nn_O)
__device__ float g_qm[B_DIM * H_DIM];        // glimpse query
__device__ float g_L[B_DIM * NK];            // clipped logits
__device__ int   g_maskmode;                 // 0=int32, 1=float32, 2=uint8

// ---------------- helpers ----------------
__device__ __forceinline__ float tanh_fast(float x) {
    // accurate (~1e-6 rel) tanh via MUFU ex2 + fast division; clamp avoids overflow
    x = fminf(fmaxf(x, -15.f), 15.f);
    float e = __expf(2.f * x);
    return __fdividef(e - 1.f, e + 1.f);
}
__device__ __forceinline__ float sigmoid_f(float x) {
    return 1.f / (1.f + __expf(-x));
}
__device__ __forceinline__ bool get_mask(const void* m, int idx) {
    int mode = g_maskmode;
    if (mode == 2) return ((const unsigned char*)m)[idx] != 0;
    if (mode == 1) return ((const float*)m)[idx] != 0.0f;
    return ((const int*)m)[idx] != 0;
}

// ---------------- mask dtype probe ----------------
__global__ void probe_mask_kernel(const unsigned int* __restrict__ m) {
    __shared__ int f_u8, f_f32;
    if (threadIdx.x == 0) { f_u8 = 0; f_f32 = 0; }
    __syncthreads();
    // 256000 mask elements; read 64000 words (covers whole buffer even if u8)
    for (int i = threadIdx.x; i < 64000; i += blockDim.x) {
        unsigned v = m[i];
        if (v == 0x3F800000u) f_f32 = 1;
        else if (v > 1u) f_u8 = 1;
    }
    __syncthreads();
    if (threadIdx.x == 0) g_maskmode = f_u8 ? 2 : (f_f32 ? 1 : 0);
}

// ---------------- LSTM gates GEMM ----------------
// gates[m,n] = sum_k query[m,k]*Wih[n,k] + sum_k state1[m,k]*Whh[n,k] + bih[n]+bhh[n]
// treated as one GEMM with K=512 (concat along K).
__global__ void lstm_gemm_kernel(const float* __restrict__ query,
                                 const float* __restrict__ state1,
                                 const float* __restrict__ Wih,
                                 const float* __restrict__ Whh,
                                 const float* __restrict__ bih,
                                 const float* __restrict__ bhh) {
    __shared__ float As[64][33];
    __shared__ float Bs[64][33];
    int tid = threadIdx.x;
    int tx = tid & 15, ty = tid >> 4;
    int m0 = blockIdx.y * 64;
    int n0 = blockIdx.x * 64;
    float acc[4][4] = {};
    for (int kt = 0; kt < 16; ++kt) {
        int kg = kt * 32;
        const float* Ap = (kg < 256) ? query : state1;
        const float* Bp = (kg < 256) ? Wih : Whh;
        int kof = kg & 255;
#pragma unroll
        for (int i = 0; i < 8; ++i) {
            int e = tid + i * 256;
            int r = e >> 5, c = e & 31;
            As[r][c] = Ap[(m0 + r) * 256 + kof + c];
            Bs[r][c] = Bp[(n0 + r) * 256 + kof + c];
        }
        __syncthreads();
#pragma unroll
        for (int kk = 0; kk < 32; ++kk) {
            float a[4], b[4];
#pragma unroll
            for (int i = 0; i < 4; ++i) a[i] = As[ty * 4 + i][kk];
#pragma unroll
            for (int j = 0; j < 4; ++j) b[j] = Bs[tx * 4 + j][kk];
#pragma unroll
            for (int i = 0; i < 4; ++i)
#pragma unroll
                for (int j = 0; j < 4; ++j)
                    acc[i][j] = fmaf(a[i], b[j], acc[i][j]);
        }
        __syncthreads();
    }
#pragma unroll
    for (int i = 0; i < 4; ++i) {
        int m = m0 + ty * 4 + i;
#pragma unroll
        for (int j = 0; j < 4; ++j) {
            int n = n0 + tx * 4 + j;
            g_gates[m * GATES_N + n] = acc[i][j] + bih[n] + bhh[n];
        }
    }
}

// ---------------- LSTM activation -> h, c ----------------
__global__ void lstm_act_kernel(const float* __restrict__ state2,
                                float* __restrict__ out) {
    int idx = blockIdx.x * 256 + threadIdx.x;       // 0..131071
    int m = idx >> 8, n = idx & 255;
    const float* g = g_gates + m * GATES_N;
    float gi = g[n], gf = g[256 + n], gg = g[512 + n], go = g[768 + n];
    float c = sigmoid_f(gf) * state2[idx] + sigmoid_f(gi) * tanh_fast(gg);
    float h = sigmoid_f(go) * tanh_fast(c);
    out[idx] = h;                                    // h at offset 0
    out[B_DIM * H_DIM + idx] = c;                    // c at offset 131072
}

// ---------------- MHA glimpse: Q, S, softmax, x ----------------
__global__ void attn_kernel(const float* __restrict__ Kt,
                            const float* __restrict__ Vt,
                            const float* __restrict__ hbuf,   // d_out (h region)
                            const float* __restrict__ nnQ,
                            const void* __restrict__ mask) {
    int p = blockIdx.x, a = blockIdx.y;
    int tid = threadIdx.x;
    int w = tid >> 5, l = tid & 31;
    __shared__ float hs[NR * H_DIM];        // 8KB
    __shared__ float Qs[NR * HD];           // 1KB
    __shared__ float Ss[NR * NK];           // 16KB
    __shared__ float xp[8][NR][HD];         // 8KB

    for (int e = tid; e < NR * H_DIM; e += 256) hs[e] = hbuf[p * NR * H_DIM + e];
    __syncthreads();

    // Q[q,d] = sum_h hs[q,h] * nnQ[a,h,d]   (scale folded in)
    {
        int q = w, d = l;
        float s = 0.f;
        const float* qw = nnQ + a * (H_DIM * HD) + d;
        const float* hr = hs + q * H_DIM;
#pragma unroll 8
        for (int c = 0; c < H_DIM; ++c) s = fmaf(hr[c], qw[c * HD], s);
        Qs[q * HD + d] = s * 0.17677669529663687f;   // 1/sqrt(32)
    }
    __syncthreads();

    // S[q,k] (thread-per-k, K row read once per block)
    const float* Kbase = Kt + ((size_t)(a * NP + p)) * NK * HD;
    int mbase = p * (NR * NK);
    for (int k = tid; k < NK; k += 256) {
        float kb[HD];
        const float4* kr = (const float4*)(Kbase + k * HD);
#pragma unroll
        for (int d4 = 0; d4 < 8; ++d4) {
            float4 v = kr[d4];
            kb[d4 * 4 + 0] = v.x; kb[d4 * 4 + 1] = v.y;
            kb[d4 * 4 + 2] = v.z; kb[d4 * 4 + 3] = v.w;
        }
#pragma unroll
        for (int q = 0; q < NR; ++q) {
            float s = 0.f;
#pragma unroll
            for (int d = 0; d < HD; ++d) s = fmaf(Qs[q * HD + d], kb[d], s);
            if (get_mask(mask, mbase + q * NK + k)) s = NEG_INF;
            Ss[q * NK + k] = s;
        }
    }
    __syncthreads();

    // softmax per q (warp w = q)
    {
        int q = w;
        float m = NEG_INF;
        for (int k = l; k < NK; k += 32) m = fmaxf(m, Ss[q * NK + k]);
#pragma unroll
        for (int o = 16; o; o >>= 1) m = fmaxf(m, __shfl_xor_sync(0xffffffffu, m, o));
        float s = 0.f;
        for (int k = l; k < NK; k += 32) {
            float e = __expf(Ss[q * NK + k] - m);
            Ss[q * NK + k] = e;
            s += e;
        }
#pragma unroll
        for (int o = 16; o; o >>= 1) s += __shfl_xor_sync(0xffffffffu, s, o);
        float inv = 1.f / s;
        for (int k = l; k < NK; k += 32) Ss[q * NK + k] *= inv;
    }
    __syncthreads();

    // x = P @ V : warp owns a k-chunk for ALL q (V read once per block)
    {
        int k0 = (NK * w) / 8, k1 = (NK * (w + 1)) / 8;
        float acc[NR];
#pragma unroll
        for (int q = 0; q < NR; ++q) acc[q] = 0.f;
        const float* Vb = Vt + ((size_t)(a * NP + p)) * NK * HD + l;
        for (int k = k0; k < k1; ++k) {
            float v = Vb[k * HD];
#pragma unroll
            for (int q = 0; q < NR; ++q) acc[q] = fmaf(Ss[q * NK + k], v, acc[q]);
        }
#pragma unroll
        for (int q = 0; q < NR; ++q) xp[w][q][l] = acc[q];
    }
    __syncthreads();
    {
        int q = w, d = l;
        float s = 0.f;
#pragma unroll
        for (int u = 0; u < 8; ++u) s += xp[u][q][d];
        g_xg[(p * NR + q) * H_DIM + a * HD + d] = s;   // [p,q, a*32+d]
    }
}

// ---------------- qm = xg @ nn_O ----------------
__global__ void qm_gemm_kernel(const float* __restrict__ O) {
    __shared__ float As[64][33];
    __shared__ float Bs[32][33];
    int tid = threadIdx.x;
    int tx = tid & 15, ty = tid >> 4;
    int m0 = blockIdx.y * 64;
    int n0 = blockIdx.x * 32;
    float acc[4][2] = {};
    for (int kt = 0; kt < 8; ++kt) {
        int k0 = kt * 32;
#pragma unroll
        for (int i = 0; i < 8; ++i) {
            int e = tid + i * 256;
            int r = e >> 5, c = e & 31;
            As[r][c] = g_xg[(m0 + r) * 256 + k0 + c];
        }
#pragma unroll
        for (int i = 0; i < 4; ++i) {
            int e = tid + i * 256;
            int r = e >> 5, c = e & 31;     // r = kk, c = n
            Bs[r][c] = O[(k0 + r) * 256 + n0 + c];
        }
        __syncthreads();
#pragma unroll
        for (int kk = 0; kk < 32; ++kk) {
            float a[4], b[2];
#pragma unroll
            for (int i = 0; i < 4; ++i) a[i] = As[ty * 4 + i][kk];
#pragma unroll
            for (int j = 0; j < 2; ++j) b[j] = Bs[kk][tx * 2 + j];
#pragma unroll
            for (int i = 0; i < 4; ++i)
#pragma unroll
                for (int j = 0; j < 2; ++j)
                    acc[i][j] = fmaf(a[i], b[j], acc[i][j]);
        }
        __syncthreads();
    }
#pragma unroll
    for (int i = 0; i < 4; ++i)
#pragma unroll
        for (int j = 0; j < 2; ++j)
            g_qm[(m0 + ty * 4 + i) * 256 + n0 + tx * 2 + j] = acc[i][j];
}

// ---------------- additive attention logits ----------------
#define KCH 50
__global__ void logits_kernel(const float* __restrict__ X,
                              const float* __restrict__ varfeat,
                              const void* __restrict__ mask,
                              const float* __restrict__ nnA,
                              const float* __restrict__ nnB,
                              const float* __restrict__ nnW) {
    int p = blockIdx.x;
    int kbase = blockIdx.y * KCH;
    int tid = threadIdx.x, w = tid >> 5, l = tid & 31;
    __shared__ float qs[NR * H_DIM];    // 8KB
    __shared__ float As[VD * H_DIM];    // 8KB
    __shared__ float Bsm[H_DIM];        // 1KB
    __shared__ float vfs[VD][KCH];      // 1.6KB
    for (int e = tid; e < NR * H_DIM; e += 256) {
        qs[e] = g_qm[p * NR * H_DIM + e];
        As[e] = nnA[e];                 // VD*H = 2048 == NR*H, same trip count
    }
    Bsm[tid] = nnB[tid];
    for (int e = tid; e < VD * KCH; e += 256) {
        int v = e / KCH, kk = e % KCH;
        vfs[v][kk] = varfeat[(p * VD + v) * NK + kbase + kk];
    }
    float Wv[8];
#pragma unroll
    for (int j = 0; j < 8; ++j) Wv[j] = nnW[l + 32 * j];
    __syncthreads();

    for (int k = kbase + w; k < kbase + KCH; k += 8) {
        int kk = k - kbase;
        const float* Xr = X + ((size_t)p * NK + k) * H_DIM;
        float base[8];
#pragma unroll
        for (int j = 0; j < 8; ++j) base[j] = Xr[l + 32 * j] + Bsm[l + 32 * j];
#pragma unroll
        for (int v = 0; v < VD; ++v) {
            float f = vfs[v][kk];
#pragma unroll
            for (int j = 0; j < 8; ++j)
                base[j] = fmaf(f, As[v * H_DIM + l + 32 * j], base[j]);
        }
        int mb = p * (NR * NK) + k;
#pragma unroll
        for (int q = 0; q < NR; ++q) {
            float out;
            if (get_mask(mask, mb + q * NK)) {
                out = NEG_INF;
            } else {
                float s = 0.f;
#pragma unroll
                for (int j = 0; j < 8; ++j)
                    s = fmaf(tanh_fast(base[j] + qs[q * H_DIM + l + 32 * j]), Wv[j], s);
#pragma unroll
                for (int o = 16; o; o >>= 1) s += __shfl_xor_sync(0xffffffffu, s, o);
                out = 10.f * tanh_fast(s);
            }
            if (l == 0) g_L[(p * NR + q) * NK + k] = out;
        }
    }
}

// ---------------- choose: argmax + log_softmax ----------------
__global__ void choose_kernel(float* __restrict__ out) {
    int w = threadIdx.x >> 5, l = threadIdx.x & 31;
    int r = blockIdx.x * 8 + w;                 // row 0..511
    const float* Lr = g_L + r * NK;
    float best = NEG_INF; int bi = NK;
    for (int k = l; k < NK; k += 32) {
        float v = Lr[k];
        if (v > best) { best = v; bi = k; }
    }
#pragma unroll
    for (int o = 16; o; o >>= 1) {
        float ov = __shfl_xor_sync(0xffffffffu, best, o);
        int oi = __shfl_xor_sync(0xffffffffu, bi, o);
        if (ov > best || (ov == best && oi < bi)) { best = ov; bi = oi; }
    }
    float s = 0.f;
    for (int k = l; k < NK; k += 32) {
        float v = Lr[k];
        if (v > NEG_INF) s += __expf(v - best);
    }
#pragma unroll
    for (int o = 16; o; o >>= 1) s += __shfl_xor_sync(0xffffffffu, s, o);
    if (l == 0) out[2 * B_DIM * H_DIM + r] = -logf(s);   // l[chosen]==best
}

// ---------------- launch ----------------
extern "C" void kernel_launch(void* const* d_in, const int* in_sizes, int n_in,
                              void* d_out, int out_size) {
    const float* X       = (const float*)d_in[0];
    const float* Kt      = (const float*)d_in[1];
    const float* Vt      = (const float*)d_in[2];
    const float* query   = (const float*)d_in[3];
    const float* state1  = (const float*)d_in[4];
    const float* state2  = (const float*)d_in[5];
    const float* varfeat = (const float*)d_in[6];
    const void*  mask    = (const void*) d_in[7];
    const float* nnQ     = (const float*)d_in[8];
    const float* nnO     = (const float*)d_in[9];
    const float* nnA     = (const float*)d_in[10];
    const float* nnB     = (const float*)d_in[11];
    const float* nnW     = (const float*)d_in[12];
    const float* Wih     = (const float*)d_in[13];
    const float* Whh     = (const float*)d_in[14];
    const float* bih     = (const float*)d_in[15];
    const float* bhh     = (const float*)d_in[16];
    float* out = (float*)d_out;

    probe_mask_kernel<<<1, 256>>>((const unsigned int*)mask);
    lstm_gemm_kernel<<<dim3(16, 8), 256>>>(query, state1, Wih, Whh, bih, bhh);
    lstm_act_kernel<<<512, 256>>>(state2, out);
    attn_kernel<<<dim3(NP, HEADS), 256>>>(Kt, Vt, out, nnQ, mask);
    qm_gemm_kernel<<<dim3(8, 8), 256>>>(nnO);
    logits_kernel<<<dim3(NP, NK / KCH), 256>>>(X, varfeat, mask, nnA, nnB, nnW);
    choose_kernel<<<64, 256>>>(out);
}

// round 2
// speedup vs baseline: 1.0724x; 1.0724x over previous
#include <cuda_runtime.h>
#include <cuda_bf16.h>
#include <math.h>

// Problem constants
#define NP 64
#define NR 8
#define NK 500
#define H_DIM 256
#define HEADS 8
#define HD 32
#define VD 8
#define B_DIM (NP*NR)          // 512
#define GATES_N (4*H_DIM)      // 1024

#define NEG_INF (__int_as_float(0xff800000))

// ---------------- scratch (no allocation allowed) ----------------
__device__ float g_gates[B_DIM * GATES_N];   // 512x1024
__device__ float g_Qg[B_DIM * H_DIM];        // projected+scaled Q, [b][a*32+d]
__device__ float g_xg[B_DIM * H_DIM];        // glimpse output (pre nn_O)
__device__ float g_qm[B_DIM * H_DIM];        // glimpse query
__device__ float g_L[B_DIM * NK];            // clipped logits
__device__ int   g_maskmode;                 // 0=int32, 1=float32, 2=uint8

// ---------------- helpers ----------------
__device__ __forceinline__ float tanh_fast(float x) {
    x = fminf(fmaxf(x, -15.f), 15.f);
    float e = __expf(2.f * x);
    return __fdividef(e - 1.f, e + 1.f);
}
__device__ __forceinline__ float sigmoid_f(float x) {
    return 1.f / (1.f + __expf(-x));
}
__device__ __forceinline__ bool get_mask(const void* m, int idx) {
    int mode = g_maskmode;
    if (mode == 2) return ((const unsigned char*)m)[idx] != 0;
    if (mode == 1) return ((const float*)m)[idx] != 0.0f;
    return ((const int*)m)[idx] != 0;
}

// ---------------- mask dtype probe ----------------
__global__ void probe_mask_kernel(const unsigned int* __restrict__ m) {
    __shared__ int f_u8, f_f32;
    if (threadIdx.x == 0) { f_u8 = 0; f_f32 = 0; }
    __syncthreads();
    for (int i = threadIdx.x; i < 64000; i += blockDim.x) {
        unsigned v = m[i];
        if (v == 0x3F800000u) f_f32 = 1;
        else if (v > 1u) f_u8 = 1;
    }
    __syncthreads();
    if (threadIdx.x == 0) g_maskmode = f_u8 ? 2 : (f_f32 ? 1 : 0);
}

// ---------------- LSTM gates GEMM ----------------
__global__ void lstm_gemm_kernel(const float* __restrict__ query,
                                 const float* __restrict__ state1,
                                 const float* __restrict__ Wih,
                                 const float* __restrict__ Whh,
                                 const float* __restrict__ bih,
                                 const float* __restrict__ bhh) {
    __shared__ float As[64][33];
    __shared__ float Bs[64][33];
    int tid = threadIdx.x;
    int tx = tid & 15, ty = tid >> 4;
    int m0 = blockIdx.y * 64;
    int n0 = blockIdx.x * 64;
    float acc[4][4] = {};
    for (int kt = 0; kt < 16; ++kt) {
        int kg = kt * 32;
        const float* Ap = (kg < 256) ? query : state1;
        const float* Bp = (kg < 256) ? Wih : Whh;
        int kof = kg & 255;
#pragma unroll
        for (int i = 0; i < 8; ++i) {
            int e = tid + i * 256;
            int r = e >> 5, c = e & 31;
            As[r][c] = Ap[(m0 + r) * 256 + kof + c];
            Bs[r][c] = Bp[(n0 + r) * 256 + kof + c];
        }
        __syncthreads();
#pragma unroll
        for (int kk = 0; kk < 32; ++kk) {
            float a[4], b[4];
#pragma unroll
            for (int i = 0; i < 4; ++i) a[i] = As[ty * 4 + i][kk];
#pragma unroll
            for (int j = 0; j < 4; ++j) b[j] = Bs[tx * 4 + j][kk];
#pragma unroll
            for (int i = 0; i < 4; ++i)
#pragma unroll
                for (int j = 0; j < 4; ++j)
                    acc[i][j] = fmaf(a[i], b[j], acc[i][j]);
        }
        __syncthreads();
    }
#pragma unroll
    for (int i = 0; i < 4; ++i) {
        int m = m0 + ty * 4 + i;
#pragma unroll
        for (int j = 0; j < 4; ++j) {
            int n = n0 + tx * 4 + j;
            g_gates[m * GATES_N + n] = acc[i][j] + bih[n] + bhh[n];
        }
    }
}

// ---------------- LSTM activation -> h, c ----------------
__global__ void lstm_act_kernel(const float* __restrict__ state2,
                                float* __restrict__ out) {
    int idx = blockIdx.x * 256 + threadIdx.x;       // 0..131071
    int m = idx >> 8, n = idx & 255;
    const float* g = g_gates + m * GATES_N;
    float gi = g[n], gf = g[256 + n], gg = g[512 + n], go = g[768 + n];
    float c = sigmoid_f(gf) * state2[idx] + sigmoid_f(gi) * tanh_fast(gg);
    float h = sigmoid_f(go) * tanh_fast(c);
    out[idx] = h;                                    // h at offset 0
    out[B_DIM * H_DIM + idx] = c;                    // c at offset 131072
}

// ---------------- Q projection GEMM: Qg = h @ nnQ (scaled) ----------------
// Qg[m][a*32+d] = (1/sqrt(32)) * sum_h hbuf[m][h] * nnQ[a][h][d]
__global__ void q_gemm_kernel(const float* __restrict__ hbuf,
                              const float* __restrict__ nnQ) {
    __shared__ float As[64][33];
    __shared__ float Bs[32][33];
    int tid = threadIdx.x;
    int tx = tid & 15, ty = tid >> 4;
    int m0 = blockIdx.y * 64;
    int n0 = blockIdx.x * 32;          // one head per n-tile (32 wide)
    int a = blockIdx.x;
    float acc[4][2] = {};
    for (int kt = 0; kt < 8; ++kt) {
        int k0 = kt * 32;
#pragma unroll
        for (int i = 0; i < 8; ++i) {
            int e = tid + i * 256;
            int r = e >> 5, c = e & 31;
            As[r][c] = hbuf[(m0 + r) * 256 + k0 + c];
        }
#pragma unroll
        for (int i = 0; i < 4; ++i) {
            int e = tid + i * 256;
            int r = e >> 5, c = e & 31;     // r = k within tile, c = d
            Bs[r][c] = nnQ[a * (H_DIM * HD) + (k0 + r) * HD + c];
        }
        __syncthreads();
#pragma unroll
        for (int kk = 0; kk < 32; ++kk) {
            float av[4], bv[2];
#pragma unroll
            for (int i = 0; i < 4; ++i) av[i] = As[ty * 4 + i][kk];
#pragma unroll
            for (int j = 0; j < 2; ++j) bv[j] = Bs[kk][tx * 2 + j];
#pragma unroll
            for (int i = 0; i < 4; ++i)
#pragma unroll
                for (int j = 0; j < 2; ++j)
                    acc[i][j] = fmaf(av[i], bv[j], acc[i][j]);
        }
        __syncthreads();
    }
#pragma unroll
    for (int i = 0; i < 4; ++i)
#pragma unroll
        for (int j = 0; j < 2; ++j)
            g_Qg[(m0 + ty * 4 + i) * 256 + n0 + tx * 2 + j] =
                acc[i][j] * 0.17677669529663687f;
}

// ---------------- MHA glimpse: S, softmax, x ----------------
__global__ __launch_bounds__(256, 4)
void attn_kernel(const float* __restrict__ Kt,
                 const float* __restrict__ Vt,
                 const void* __restrict__ mask) {
    int p = blockIdx.x, a = blockIdx.y;
    int tid = threadIdx.x;
    int w = tid >> 5, l = tid & 31;
    __shared__ float Qs[NR * HD];           // 1KB
    __shared__ float Ss[NR * NK];           // 16KB
    __shared__ float xp[8][NR][HD];         // 8KB

    // load precomputed, scaled Q tile: rows p*8+q, cols a*32+d
    if (tid < NR * HD) {
        int q = tid >> 5, d = tid & 31;
        Qs[tid] = g_Qg[(p * NR + q) * H_DIM + a * HD + d];
    }
    __syncthreads();

    // S[q,k] : thread-per-k, acc[8] per float4 chunk of K (low regs)
    const float* Kbase = Kt + ((size_t)(a * NP + p)) * NK * HD;
    int mbase = p * (NR * NK);
    for (int k = tid; k < NK; k += 256) {
        const float4* kr = (const float4*)(Kbase + k * HD);
        float acc[NR] = {};
#pragma unroll
        for (int d4 = 0; d4 < 8; ++d4) {
            float4 kv = kr[d4];
#pragma unroll
            for (int q = 0; q < NR; ++q) {
                float4 qv = *(const float4*)(Qs + q * HD + d4 * 4);
                acc[q] = fmaf(qv.x, kv.x,
                         fmaf(qv.y, kv.y,
                         fmaf(qv.z, kv.z,
                         fmaf(qv.w, kv.w, acc[q]))));
            }
        }
#pragma unroll
        for (int q = 0; q < NR; ++q) {
            Ss[q * NK + k] = get_mask(mask, mbase + q * NK + k) ? NEG_INF : acc[q];
        }
    }
    __syncthreads();

    // softmax per q (warp w = q)
    {
        int q = w;
        float m = NEG_INF;
        for (int k = l; k < NK; k += 32) m = fmaxf(m, Ss[q * NK + k]);
#pragma unroll
        for (int o = 16; o; o >>= 1) m = fmaxf(m, __shfl_xor_sync(0xffffffffu, m, o));
        float s = 0.f;
        for (int k = l; k < NK; k += 32) {
            float e = __expf(Ss[q * NK + k] - m);
            Ss[q * NK + k] = e;
            s += e;
        }
#pragma unroll
        for (int o = 16; o; o >>= 1) s += __shfl_xor_sync(0xffffffffu, s, o);
        float inv = 1.f / s;
        for (int k = l; k < NK; k += 32) Ss[q * NK + k] *= inv;
    }
    __syncthreads();

    // x = P @ V : warp owns a k-chunk for ALL q (V read once per block)
    {
        int k0 = (NK * w) / 8, k1 = (NK * (w + 1)) / 8;
        float acc[NR] = {};
        const float* Vb = Vt + ((size_t)(a * NP + p)) * NK * HD + l;
        for (int k = k0; k < k1; ++k) {
            float v = Vb[k * HD];
#pragma unroll
            for (int q = 0; q < NR; ++q) acc[q] = fmaf(Ss[q * NK + k], v, acc[q]);
        }
#pragma unroll
        for (int q = 0; q < NR; ++q) xp[w][q][l] = acc[q];
    }
    __syncthreads();
    {
        int q = w, d = l;
        float s = 0.f;
#pragma unroll
        for (int u = 0; u < 8; ++u) s += xp[u][q][d];
        g_xg[(p * NR + q) * H_DIM + a * HD + d] = s;   // [p,q, a*32+d]
    }
}

// ---------------- qm = xg @ nn_O ----------------
__global__ void qm_gemm_kernel(const float* __restrict__ O) {
    __shared__ float As[64][33];
    __shared__ float Bs[32][33];
    int tid = threadIdx.x;
    int tx = tid & 15, ty = tid >> 4;
    int m0 = blockIdx.y * 64;
    int n0 = blockIdx.x * 32;
    float acc[4][2] = {};
    for (int kt = 0; kt < 8; ++kt) {
        int k0 = kt * 32;
#pragma unroll
        for (int i = 0; i < 8; ++i) {
            int e = tid + i * 256;
            int r = e >> 5, c = e & 31;
            As[r][c] = g_xg[(m0 + r) * 256 + k0 + c];
        }
#pragma unroll
        for (int i = 0; i < 4; ++i) {
            int e = tid + i * 256;
            int r = e >> 5, c = e & 31;     // r = kk, c = n
            Bs[r][c] = O[(k0 + r) * 256 + n0 + c];
        }
        __syncthreads();
#pragma unroll
        for (int kk = 0; kk < 32; ++kk) {
            float av[4], bv[2];
#pragma unroll
            for (int i = 0; i < 4; ++i) av[i] = As[ty * 4 + i][kk];
#pragma unroll
            for (int j = 0; j < 2; ++j) bv[j] = Bs[kk][tx * 2 + j];
#pragma unroll
            for (int i = 0; i < 4; ++i)
#pragma unroll
                for (int j = 0; j < 2; ++j)
                    acc[i][j] = fmaf(av[i], bv[j], acc[i][j]);
        }
        __syncthreads();
    }
#pragma unroll
    for (int i = 0; i < 4; ++i)
#pragma unroll
        for (int j = 0; j < 2; ++j)
            g_qm[(m0 + ty * 4 + i) * 256 + n0 + tx * 2 + j] = acc[i][j];
}

// ---------------- additive attention logits ----------------
#define KCH 50
__global__ void logits_kernel(const float* __restrict__ X,
                              const float* __restrict__ varfeat,
                              const void* __restrict__ mask,
                              const float* __restrict__ nnA,
                              const float* __restrict__ nnB,
                              const float* __restrict__ nnW) {
    int p = blockIdx.x;
    int kbase = blockIdx.y * KCH;
    int tid = threadIdx.x, w = tid >> 5, l = tid & 31;
    __shared__ float qs[NR * H_DIM];    // 8KB
    __shared__ float As[VD * H_DIM];    // 8KB
    __shared__ float Bsm[H_DIM];        // 1KB
    __shared__ float vfs[VD][KCH];      // 1.6KB
    for (int e = tid; e < NR * H_DIM; e += 256) {
        qs[e] = g_qm[p * NR * H_DIM + e];
        As[e] = nnA[e];
    }
    Bsm[tid] = nnB[tid];
    for (int e = tid; e < VD * KCH; e += 256) {
        int v = e / KCH, kk = e % KCH;
        vfs[v][kk] = varfeat[(p * VD + v) * NK + kbase + kk];
    }
    float Wv[8];
#pragma unroll
    for (int j = 0; j < 8; ++j) Wv[j] = nnW[l + 32 * j];
    __syncthreads();

    for (int k = kbase + w; k < kbase + KCH; k += 8) {
        int kk = k - kbase;
        const float* Xr = X + ((size_t)p * NK + k) * H_DIM;
        float base[8];
#pragma unroll
        for (int j = 0; j < 8; ++j) base[j] = Xr[l + 32 * j] + Bsm[l + 32 * j];
#pragma unroll
        for (int v = 0; v < VD; ++v) {
            float f = vfs[v][kk];
#pragma unroll
            for (int j = 0; j < 8; ++j)
                base[j] = fmaf(f, As[v * H_DIM + l + 32 * j], base[j]);
        }
        int mb = p * (NR * NK) + k;
#pragma unroll
        for (int q = 0; q < NR; ++q) {
            float out;
            if (get_mask(mask, mb + q * NK)) {
                out = NEG_INF;
            } else {
                float s = 0.f;
#pragma unroll
                for (int j = 0; j < 8; ++j)
                    s = fmaf(tanh_fast(base[j] + qs[q * H_DIM + l + 32 * j]), Wv[j], s);
#pragma unroll
                for (int o = 16; o; o >>= 1) s += __shfl_xor_sync(0xffffffffu, s, o);
                out = 10.f * tanh_fast(s);
            }
            if (l == 0) g_L[(p * NR + q) * NK + k] = out;
        }
    }
}

// ---------------- choose: argmax + log_softmax ----------------
__global__ void choose_kernel(float* __restrict__ out) {
    int w = threadIdx.x >> 5, l = threadIdx.x & 31;
    int r = blockIdx.x * 8 + w;                 // row 0..511
    const float* Lr = g_L + r * NK;
    float best = NEG_INF; int bi = NK;
    for (int k = l; k < NK; k += 32) {
        float v = Lr[k];
        if (v > best) { best = v; bi = k; }
    }
#pragma unroll
    for (int o = 16; o; o >>= 1) {
        float ov = __shfl_xor_sync(0xffffffffu, best, o);
        int oi = __shfl_xor_sync(0xffffffffu, bi, o);
        if (ov > best || (ov == best && oi < bi)) { best = ov; bi = oi; }
    }
    float s = 0.f;
    for (int k = l; k < NK; k += 32) {
        float v = Lr[k];
        if (v > NEG_INF) s += __expf(v - best);
    }
#pragma unroll
    for (int o = 16; o; o >>= 1) s += __shfl_xor_sync(0xffffffffu, s, o);
    if (l == 0) out[2 * B_DIM * H_DIM + r] = -logf(s);   // l[chosen]==best
}

// ---------------- launch ----------------
extern "C" void kernel_launch(void* const* d_in, const int* in_sizes, int n_in,
                              void* d_out, int out_size) {
    const float* X       = (const float*)d_in[0];
    const float* Kt      = (const float*)d_in[1];
    const float* Vt      = (const float*)d_in[2];
    const float* query   = (const float*)d_in[3];
    const float* state1  = (const float*)d_in[4];
    const float* state2  = (const float*)d_in[5];
    const float* varfeat = (const float*)d_in[6];
    const void*  mask    = (const void*) d_in[7];
    const float* nnQ     = (const float*)d_in[8];
    const float* nnO     = (const float*)d_in[9];
    const float* nnA     = (const float*)d_in[10];
    const float* nnB     = (const float*)d_in[11];
    const float* nnW     = (const float*)d_in[12];
    const float* Wih     = (const float*)d_in[13];
    const float* Whh     = (const float*)d_in[14];
    const float* bih     = (const float*)d_in[15];
    const float* bhh     = (const float*)d_in[16];
    float* out = (float*)d_out;

    probe_mask_kernel<<<1, 256>>>((const unsigned int*)mask);
    lstm_gemm_kernel<<<dim3(16, 8), 256>>>(query, state1, Wih, Whh, bih, bhh);
    lstm_act_kernel<<<512, 256>>>(state2, out);
    q_gemm_kernel<<<dim3(8, 8), 256>>>(out, nnQ);
    attn_kernel<<<dim3(NP, HEADS), 256>>>(Kt, Vt, mask);
    qm_gemm_kernel<<<dim3(8, 8), 256>>>(nnO);
    logits_kernel<<<dim3(NP, NK / KCH), 256>>>(X, varfeat, mask, nnA, nnB, nnW);
    choose_kernel<<<64, 256>>>(out);
}

// round 4
// speedup vs baseline: 1.2218x; 1.1393x over previous
#include <cuda_runtime.h>
#include <cuda_bf16.h>
#include <math.h>

// Problem constants
#define NP 64
#define NR 8
#define NK 500
#define H_DIM 256
#define HEADS 8
#define HD 32
#define VD 8
#define B_DIM (NP*NR)          // 512
#define GATES_N (4*H_DIM)      // 1024

#define NEG_INF (__int_as_float(0xff800000))

// ---------------- scratch (no allocation allowed) ----------------
__device__ float g_gates[B_DIM * GATES_N];   // 512x1024
__device__ float g_Qg[B_DIM * H_DIM];        // projected+scaled Q
__device__ float g_xg[B_DIM * H_DIM];        // glimpse output (pre nn_O)
__device__ float g_qm[B_DIM * H_DIM];        // glimpse query
__device__ float g_L[B_DIM * NK];            // clipped logits
__device__ unsigned g_flags;                 // bit0: f32 pattern seen, bit1: u8 pattern seen

// ---------------- helpers ----------------
__device__ __forceinline__ float tanh_fast(float x) {      // accurate (~1e-7)
    x = fminf(fmaxf(x, -15.f), 15.f);
    float e = __expf(2.f * x);
    return __fdividef(e - 1.f, e + 1.f);
}
__device__ __forceinline__ float tanh_approx(float x) {    // MUFU.TANH, ~5e-4
    float y;
    asm("tanh.approx.f32 %0, %1;" : "=f"(y) : "f"(x));
    return y;
}
__device__ __forceinline__ float sigmoid_f(float x) {
    return 1.f / (1.f + __expf(-x));
}
__device__ __forceinline__ int load_maskmode() {
    unsigned f = g_flags;
    return (f & 2u) ? 2 : ((f & 1u) ? 1 : 0);
}
__device__ __forceinline__ bool get_mask(const void* m, int idx, int mode) {
    if (mode == 2) return ((const unsigned char*)m)[idx] != 0;
    if (mode == 1) return ((const float*)m)[idx] != 0.0f;
    return ((const int*)m)[idx] != 0;
}

// ---------------- mask dtype probe (idempotent, 64 blocks) ----------------
__global__ void probe_mask_kernel(const unsigned int* __restrict__ m) {
    unsigned local = 0;
    int base = blockIdx.x * 1000;                 // 64 blocks x 1000 words = 64000
    for (int i = threadIdx.x; i < 1000; i += 256) {
        unsigned v = m[base + i];
        if (v == 0x3F800000u) local |= 1u;
        else if (v > 1u) local |= 2u;
    }
#pragma unroll
    for (int o = 16; o; o >>= 1) local |= __shfl_xor_sync(0xffffffffu, local, o);
    if ((threadIdx.x & 31) == 0 && local) atomicOr(&g_flags, local);
}

// ---------------- LSTM gates GEMM (reg double-buffered) ----------------
__global__ __launch_bounds__(256)
void lstm_gemm_kernel(const float* __restrict__ query,
                      const float* __restrict__ state1,
                      const float* __restrict__ Wih,
                      const float* __restrict__ Whh,
                      const float* __restrict__ bih,
                      const float* __restrict__ bhh) {
    __shared__ float As[64][33];
    __shared__ float Bs[64][33];
    int tid = threadIdx.x;
    int tx = tid & 15, ty = tid >> 4;
    int m0 = blockIdx.y * 64;
    int n0 = blockIdx.x * 64;
    int r = tid >> 5, c = tid & 31;
    float acc[4][4] = {};
    float ra[8], rb[8];
    // preload kt=0
    {
        const float* Ap = query; const float* Bp = Wih;
#pragma unroll
        for (int i = 0; i < 8; ++i) {
            ra[i] = Ap[(m0 + r + i * 8) * 256 + c];
            rb[i] = Bp[(n0 + r + i * 8) * 256 + c];
        }
    }
    for (int kt = 0; kt < 16; ++kt) {
#pragma unroll
        for (int i = 0; i < 8; ++i) {
            As[r + i * 8][c] = ra[i];
            Bs[r + i * 8][c] = rb[i];
        }
        __syncthreads();
        if (kt < 15) {
            int kg = (kt + 1) * 32;
            const float* Ap = (kg < 256) ? query : state1;
            const float* Bp = (kg < 256) ? Wih : Whh;
            int kof = kg & 255;
#pragma unroll
            for (int i = 0; i < 8; ++i) {
                ra[i] = Ap[(m0 + r + i * 8) * 256 + kof + c];
                rb[i] = Bp[(n0 + r + i * 8) * 256 + kof + c];
            }
        }
#pragma unroll
        for (int kk = 0; kk < 32; ++kk) {
            float a[4], b[4];
#pragma unroll
            for (int i = 0; i < 4; ++i) a[i] = As[ty * 4 + i][kk];
#pragma unroll
            for (int j = 0; j < 4; ++j) b[j] = Bs[tx * 4 + j][kk];
#pragma unroll
            for (int i = 0; i < 4; ++i)
#pragma unroll
                for (int j = 0; j < 4; ++j)
                    acc[i][j] = fmaf(a[i], b[j], acc[i][j]);
        }
        __syncthreads();
    }
#pragma unroll
    for (int i = 0; i < 4; ++i) {
        int m = m0 + ty * 4 + i;
#pragma unroll
        for (int j = 0; j < 4; ++j) {
            int n = n0 + tx * 4 + j;
            g_gates[m * GATES_N + n] = acc[i][j] + bih[n] + bhh[n];
        }
    }
}

// ---------------- LSTM activation -> h, c ----------------
__global__ void lstm_act_kernel(const float* __restrict__ state2,
                                float* __restrict__ out) {
    int idx = blockIdx.x * 256 + threadIdx.x;       // 0..131071
    int m = idx >> 8, n = idx & 255;
    const float* g = g_gates + m * GATES_N;
    float gi = g[n], gf = g[256 + n], gg = g[512 + n], go = g[768 + n];
    float c = sigmoid_f(gf) * state2[idx] + sigmoid_f(gi) * tanh_fast(gg);
    float h = sigmoid_f(go) * tanh_fast(c);
    out[idx] = h;                                    // h at offset 0
    out[B_DIM * H_DIM + idx] = c;                    // c at offset 131072
}

// ---------------- generic 512x32-per-head GEMM (q proj / qm) --------------
// C[m][n0+j] = scale * sum_k A[m][k] * Bmat[(koffs)+k*HD + j] layout varies,
// so keep two kernels but both reg double-buffered.
__global__ __launch_bounds__(256)
void q_gemm_kernel(const float* __restrict__ hbuf,
                   const float* __restrict__ nnQ) {
    __shared__ float As[64][33];
    __shared__ float Bs[32][33];
    int tid = threadIdx.x;
    int tx = tid & 15, ty = tid >> 4;
    int m0 = blockIdx.y * 64;
    int a = blockIdx.x;
    int n0 = a * 32;
    int r = tid >> 5, c = tid & 31;
    float acc[4][2] = {};
    float ra[8], rb[4];
#pragma unroll
    for (int i = 0; i < 8; ++i) ra[i] = hbuf[(m0 + r + i * 8) * 256 + c];
#pragma unroll
    for (int i = 0; i < 4; ++i)
        rb[i] = nnQ[a * (H_DIM * HD) + (r + i * 8) * HD + c];
    for (int kt = 0; kt < 8; ++kt) {
#pragma unroll
        for (int i = 0; i < 8; ++i) As[r + i * 8][c] = ra[i];
#pragma unroll
        for (int i = 0; i < 4; ++i) Bs[r + i * 8][c] = rb[i];
        __syncthreads();
        if (kt < 7) {
            int k0 = (kt + 1) * 32;
#pragma unroll
            for (int i = 0; i < 8; ++i) ra[i] = hbuf[(m0 + r + i * 8) * 256 + k0 + c];
#pragma unroll
            for (int i = 0; i < 4; ++i)
                rb[i] = nnQ[a * (H_DIM * HD) + (k0 + r + i * 8) * HD + c];
        }
#pragma unroll
        for (int kk = 0; kk < 32; ++kk) {
            float av[4], bv[2];
#pragma unroll
            for (int i = 0; i < 4; ++i) av[i] = As[ty * 4 + i][kk];
#pragma unroll
            for (int j = 0; j < 2; ++j) bv[j] = Bs[kk][tx * 2 + j];
#pragma unroll
            for (int i = 0; i < 4; ++i)
#pragma unroll
                for (int j = 0; j < 2; ++j)
                    acc[i][j] = fmaf(av[i], bv[j], acc[i][j]);
        }
        __syncthreads();
    }
#pragma unroll
    for (int i = 0; i < 4; ++i)
#pragma unroll
        for (int j = 0; j < 2; ++j)
            g_Qg[(m0 + ty * 4 + i) * 256 + n0 + tx * 2 + j] =
                acc[i][j] * 0.17677669529663687f;
}

__global__ __launch_bounds__(256)
void qm_gemm_kernel(const float* __restrict__ O) {
    __shared__ float As[64][33];
    __shared__ float Bs[32][33];
    int tid = threadIdx.x;
    int tx = tid & 15, ty = tid >> 4;
    int m0 = blockIdx.y * 64;
    int n0 = blockIdx.x * 32;
    int r = tid >> 5, c = tid & 31;
    float acc[4][2] = {};
    float ra[8], rb[4];
#pragma unroll
    for (int i = 0; i < 8; ++i) ra[i] = g_xg[(m0 + r + i * 8) * 256 + c];
#pragma unroll
    for (int i = 0; i < 4; ++i) rb[i] = O[(r + i * 8) * 256 + n0 + c];
    for (int kt = 0; kt < 8; ++kt) {
#pragma unroll
        for (int i = 0; i < 8; ++i) As[r + i * 8][c] = ra[i];
#pragma unroll
        for (int i = 0; i < 4; ++i) Bs[r + i * 8][c] = rb[i];
        __syncthreads();
        if (kt < 7) {
            int k0 = (kt + 1) * 32;
#pragma unroll
            for (int i = 0; i < 8; ++i) ra[i] = g_xg[(m0 + r + i * 8) * 256 + k0 + c];
#pragma unroll
            for (int i = 0; i < 4; ++i) rb[i] = O[(k0 + r + i * 8) * 256 + n0 + c];
        }
#pragma unroll
        for (int kk = 0; kk < 32; ++kk) {
            float av[4], bv[2];
#pragma unroll
            for (int i = 0; i < 4; ++i) av[i] = As[ty * 4 + i][kk];
#pragma unroll
            for (int j = 0; j < 2; ++j) bv[j] = Bs[kk][tx * 2 + j];
#pragma unroll
            for (int i = 0; i < 4; ++i)
#pragma unroll
                for (int j = 0; j < 2; ++j)
                    acc[i][j] = fmaf(av[i], bv[j], acc[i][j]);
        }
        __syncthreads();
    }
#pragma unroll
    for (int i = 0; i < 4; ++i)
#pragma unroll
        for (int j = 0; j < 2; ++j)
            g_qm[(m0 + ty * 4 + i) * 256 + n0 + tx * 2 + j] = acc[i][j];
}

// ---------------- MHA glimpse: S, softmax, x ----------------
__global__ __launch_bounds__(256, 4)
void attn_kernel(const float* __restrict__ Kt,
                 const float* __restrict__ Vt,
                 const void* __restrict__ mask) {
    int p = blockIdx.x, a = blockIdx.y;
    int tid = threadIdx.x;
    int w = tid >> 5, l = tid & 31;
    __shared__ float Qs[NR * HD];           // 1KB
    __shared__ float Ss[NK * NR];           // 16KB, transposed: [k][q]
    __shared__ float xp[8][NR][HD];         // 8KB
    __shared__ float sinv[NR];
    int mode = load_maskmode();

    // load precomputed, scaled Q tile
    Qs[tid] = g_Qg[(p * NR + (tid >> 5)) * H_DIM + a * HD + (tid & 31)];
    __syncthreads();

    // S pass: thread-per-k, stores 2x STS.128 per k
    const float* Kbase = Kt + ((size_t)(a * NP + p)) * NK * HD;
    for (int k = tid; k < NK; k += 256) {
        const float4* kr = (const float4*)(Kbase + k * HD);
        float acc[NR] = {};
#pragma unroll
        for (int d4 = 0; d4 < 8; ++d4) {
            float4 kv = kr[d4];
#pragma unroll
            for (int q = 0; q < NR; ++q) {
                float4 qv = *(const float4*)(Qs + q * HD + d4 * 4);
                acc[q] = fmaf(qv.x, kv.x,
                         fmaf(qv.y, kv.y,
                         fmaf(qv.z, kv.z,
                         fmaf(qv.w, kv.w, acc[q]))));
            }
        }
        *(float4*)&Ss[k * 8]     = make_float4(acc[0], acc[1], acc[2], acc[3]);
        *(float4*)&Ss[k * 8 + 4] = make_float4(acc[4], acc[5], acc[6], acc[7]);
    }
    __syncthreads();

    // softmax per q (warp w = q); mask applied here with coalesced reads
    {
        int q = w;
        int mbase = p * (NR * NK) + q * NK;
        float m = NEG_INF;
        for (int k = l; k < NK; k += 32) {
            float v = Ss[k * 8 + q];
            if (get_mask(mask, mbase + k, mode)) { v = NEG_INF; Ss[k * 8 + q] = v; }
            m = fmaxf(m, v);
        }
#pragma unroll
        for (int o = 16; o; o >>= 1) m = fmaxf(m, __shfl_xor_sync(0xffffffffu, m, o));
        float s = 0.f;
        for (int k = l; k < NK; k += 32) {
            float e = __expf(Ss[k * 8 + q] - m);
            Ss[k * 8 + q] = e;
            s += e;
        }
#pragma unroll
        for (int o = 16; o; o >>= 1) s += __shfl_xor_sync(0xffffffffu, s, o);
        if (l == 0) sinv[q] = 1.f / s;
    }
    __syncthreads();

    // x = P @ V : warp owns a k-chunk for ALL q; 2x LDS.128 broadcast per k
    {
        int k0 = (NK * w) / 8, k1 = (NK * (w + 1)) / 8;
        float acc[NR] = {};
        const float* Vb = Vt + ((size_t)(a * NP + p)) * NK * HD + l;
        for (int k = k0; k < k1; ++k) {
            float v = Vb[k * HD];
            float4 p0 = *(const float4*)&Ss[k * 8];
            float4 p1 = *(const float4*)&Ss[k * 8 + 4];
            acc[0] = fmaf(p0.x, v, acc[0]);
            acc[1] = fmaf(p0.y, v, acc[1]);
            acc[2] = fmaf(p0.z, v, acc[2]);
            acc[3] = fmaf(p0.w, v, acc[3]);
            acc[4] = fmaf(p1.x, v, acc[4]);
            acc[5] = fmaf(p1.y, v, acc[5]);
            acc[6] = fmaf(p1.z, v, acc[6]);
            acc[7] = fmaf(p1.w, v, acc[7]);
        }
#pragma unroll
        for (int q = 0; q < NR; ++q) xp[w][q][l] = acc[q];
    }
    __syncthreads();
    {
        int q = w, d = l;
        float s = 0.f;
#pragma unroll
        for (int u = 0; u < 8; ++u) s += xp[u][q][d];
        g_xg[(p * NR + q) * H_DIM + a * HD + d] = s * sinv[q];
    }
}

// ---------------- additive attention logits ----------------
#define KCH 50
__global__ void logits_kernel(const float* __restrict__ X,
                              const float* __restrict__ varfeat,
                              const void* __restrict__ mask,
                              const float* __restrict__ nnA,
                              const float* __restrict__ nnB,
                              const float* __restrict__ nnW) {
    int p = blockIdx.x;
    int kbase = blockIdx.y * KCH;
    int tid = threadIdx.x, w = tid >> 5, l = tid & 31;
    __shared__ float qs[NR * H_DIM];    // 8KB
    __shared__ float As[VD * H_DIM];    // 8KB
    __shared__ float Bsm[H_DIM];        // 1KB
    __shared__ float vfs[VD][KCH];      // 1.6KB
    int mode = load_maskmode();
    for (int e = tid; e < NR * H_DIM; e += 256) {
        qs[e] = g_qm[p * NR * H_DIM + e];
        As[e] = nnA[e];
    }
    Bsm[tid] = nnB[tid];
    for (int e = tid; e < VD * KCH; e += 256) {
        int v = e / KCH, kk = e % KCH;
        vfs[v][kk] = varfeat[(p * VD + v) * NK + kbase + kk];
    }
    float Wv[8];
#pragma unroll
    for (int j = 0; j < 8; ++j) Wv[j] = nnW[l + 32 * j];
    __syncthreads();

    for (int k = kbase + w; k < kbase + KCH; k += 8) {
        int kk = k - kbase;
        const float* Xr = X + ((size_t)p * NK + k) * H_DIM;
        float base[8];
#pragma unroll
        for (int j = 0; j < 8; ++j) base[j] = Xr[l + 32 * j] + Bsm[l + 32 * j];
#pragma unroll
        for (int v = 0; v < VD; ++v) {
            float f = vfs[v][kk];
#pragma unroll
            for (int j = 0; j < 8; ++j)
                base[j] = fmaf(f, As[v * H_DIM + l + 32 * j], base[j]);
        }
        int mb = p * (NR * NK) + k;
#pragma unroll
        for (int q = 0; q < NR; ++q) {
            float out;
            if (get_mask(mask, mb + q * NK, mode)) {
                out = NEG_INF;
            } else {
                float s = 0.f;
#pragma unroll
                for (int j = 0; j < 8; ++j)
                    s = fmaf(tanh_approx(base[j] + qs[q * H_DIM + l + 32 * j]), Wv[j], s);
#pragma unroll
                for (int o = 16; o; o >>= 1) s += __shfl_xor_sync(0xffffffffu, s, o);
                out = 10.f * tanh_fast(s);
            }
            if (l == 0) g_L[(p * NR + q) * NK + k] = out;
        }
    }
}

// ---------------- choose: argmax + log_softmax ----------------
__global__ void choose_kernel(float* __restrict__ out) {
    int w = threadIdx.x >> 5, l = threadIdx.x & 31;
    int r = blockIdx.x * 8 + w;                 // row 0..511
    const float* Lr = g_L + r * NK;
    float best = NEG_INF; int bi = NK;
    for (int k = l; k < NK; k += 32) {
        float v = Lr[k];
        if (v > best) { best = v; bi = k; }
    }
#pragma unroll
    for (int o = 16; o; o >>= 1) {
        float ov = __shfl_xor_sync(0xffffffffu, best, o);
        int oi = __shfl_xor_sync(0xffffffffu, bi, o);
        if (ov > best || (ov == best && oi < bi)) { best = ov; bi = oi; }
    }
    float s = 0.f;
    for (int k = l; k < NK; k += 32) {
        float v = Lr[k];
        if (v > NEG_INF) s += __expf(v - best);
    }
#pragma unroll
    for (int o = 16; o; o >>= 1) s += __shfl_xor_sync(0xffffffffu, s, o);
    if (l == 0) out[2 * B_DIM * H_DIM + r] = -logf(s);   // l[chosen]==best
}

// ---------------- launch ----------------
extern "C" void kernel_launch(void* const* d_in, const int* in_sizes, int n_in,
                              void* d_out, int out_size) {
    const float* X       = (const float*)d_in[0];
    const float* Kt      = (const float*)d_in[1];
    const float* Vt      = (const float*)d_in[2];
    const float* query   = (const float*)d_in[3];
    const float* state1  = (const float*)d_in[4];
    const float* state2  = (const float*)d_in[5];
    const float* varfeat = (const float*)d_in[6];
    const void*  mask    = (const void*) d_in[7];
    const float* nnQ     = (const float*)d_in[8];
    const float* nnO     = (const float*)d_in[9];
    const float* nnA     = (const float*)d_in[10];
    const float* nnB     = (const float*)d_in[11];
    const float* nnW     = (const float*)d_in[12];
    const float* Wih     = (const float*)d_in[13];
    const float* Whh     = (const float*)d_in[14];
    const float* bih     = (const float*)d_in[15];
    const float* bhh     = (const float*)d_in[16];
    float* out = (float*)d_out;

    probe_mask_kernel<<<64, 256>>>((const unsigned int*)mask);
    lstm_gemm_kernel<<<dim3(16, 8), 256>>>(query, state1, Wih, Whh, bih, bhh);
    lstm_act_kernel<<<512, 256>>>(state2, out);
    q_gemm_kernel<<<dim3(8, 8), 256>>>(out, nnQ);
    attn_kernel<<<dim3(NP, HEADS), 256>>>(Kt, Vt, mask);
    qm_gemm_kernel<<<dim3(8, 8), 256>>>(nnO);
    logits_kernel<<<dim3(NP, NK / KCH), 256>>>(X, varfeat, mask, nnA, nnB, nnW);
    choose_kernel<<<64, 256>>>(out);
}

// round 5
// speedup vs baseline: 1.3951x; 1.1418x over previous
#include <cuda_runtime.h>
#include <cuda_bf16.h>
#include <math.h>

// Problem constants
#define NP 64
#define NR 8
#define NK 500
#define H_DIM 256
#define HEADS 8
#define HD 32
#define VD 8
#define B_DIM (NP*NR)          // 512
#define KCH 50

#define GRID 264
#define TPB 256

#define NEG_INF (__int_as_float(0xff800000))

// ---------------- scratch (no allocation allowed) ----------------
__device__ float g_Qg[B_DIM * H_DIM];        // projected+scaled Q
__device__ float g_xg[B_DIM * H_DIM];        // glimpse output (pre nn_O)
__device__ float g_qm[B_DIM * H_DIM];        // glimpse query
__device__ float g_L[B_DIM * NK];            // clipped logits
__device__ unsigned g_flags;                 // bit0: f32 seen, bit1: u8 seen (idempotent)
__device__ unsigned g_cnt = 0;               // barrier arrivals (self-resetting)
__device__ unsigned g_gen = 0;               // barrier generation (monotonic)

// ---------------- global software barrier (replay-safe) ----------------
__device__ __forceinline__ void gsync() {
    __syncthreads();
    if (threadIdx.x == 0) {
        volatile unsigned* vgen = &g_gen;
        __threadfence();
        unsigned my = *vgen;
        unsigned v = atomicAdd(&g_cnt, 1u);
        if (v == (unsigned)(GRID - 1)) {
            g_cnt = 0u;                 // reset for next barrier / next replay
            __threadfence();
            atomicAdd(&g_gen, 1u);      // release
        } else {
            while (*vgen == my) __nanosleep(32);
        }
        __threadfence();
    }
    __syncthreads();
}

// ---------------- helpers ----------------
__device__ __forceinline__ float tanh_fast(float x) {      // accurate (~1e-7)
    x = fminf(fmaxf(x, -15.f), 15.f);
    float e = __expf(2.f * x);
    return __fdividef(e - 1.f, e + 1.f);
}
__device__ __forceinline__ float tanh_approx(float x) {    // MUFU.TANH
    float y;
    asm("tanh.approx.f32 %0, %1;" : "=f"(y) : "f"(x));
    return y;
}
__device__ __forceinline__ float sigmoid_f(float x) {
    return 1.f / (1.f + __expf(-x));
}
__device__ __forceinline__ int load_maskmode() {
    unsigned f = *(volatile unsigned*)&g_flags;
    return (f & 2u) ? 2 : ((f & 1u) ? 1 : 0);
}
__device__ __forceinline__ bool get_mask(const void* m, int idx, int mode) {
    if (mode == 2) return ((const unsigned char*)m)[idx] != 0;
    if (mode == 1) return ((const float*)m)[idx] != 0.0f;
    return ((const int*)m)[idx] != 0;
}

// ---------------- shared memory union ----------------
union SmemU {
    struct { float As[32][33]; float Bs[64][33]; } lstm;                       // 12.7KB
    struct { float As[16][33]; float Bs[32][33]; } gem;                        // 6.3KB
    struct { float Qs[NR*HD]; float Ss[NK*NR]; float xp[8][NR][HD]; float sinv[NR]; } attn; // 25.2KB
    struct { float qs[NR*H_DIM]; float As[VD*H_DIM]; float B[H_DIM]; float vfs[VD][KCH]; } lg; // 18.6KB
};

// =========================== stages ===========================

__device__ void stage_probe(const unsigned int* __restrict__ m) {
    unsigned local = 0;
    for (int i = blockIdx.x * TPB + threadIdx.x; i < 64000; i += GRID * TPB) {
        unsigned v = m[i];
        if (v == 0x3F800000u) local |= 1u;
        else if (v > 1u) local |= 2u;
    }
#pragma unroll
    for (int o = 16; o; o >>= 1) local |= __shfl_xor_sync(0xffffffffu, local, o);
    if ((threadIdx.x & 31) == 0 && local) atomicOr(&g_flags, local);
}

// LSTM GEMM + fused activation. Tile: 32 m x (16 cols x 4 gates).
// 256 tiles: mt = tile>>4 (16), ct = tile&15 (16).
__device__ void stage_lstm(const float* __restrict__ query,
                           const float* __restrict__ state1,
                           const float* __restrict__ Wih,
                           const float* __restrict__ Whh,
                           const float* __restrict__ bih,
                           const float* __restrict__ bhh,
                           const float* __restrict__ state2,
                           float* __restrict__ out, SmemU* sm) {
    int tile = blockIdx.x;
    if (tile >= 256) return;
    int m0 = (tile >> 4) * 32;
    int colbase = (tile & 15) * 16;
    int tid = threadIdx.x;
    int r = tid >> 5, c = tid & 31;          // loader coords
    int ty = tid >> 4, tx = tid & 15;        // compute coords: m pair, col
    float acc[2][4] = {};                    // [m][gate]
    float ra[4], rb[8];
    // jrow -> global weight row
    int nrow[8];
#pragma unroll
    for (int i = 0; i < 8; ++i) {
        int j = r + i * 8;                   // 0..63
        nrow[i] = (j >> 4) * 256 + colbase + (j & 15);
    }
    // preload kt=0
#pragma unroll
    for (int i = 0; i < 4; ++i) ra[i] = query[(m0 + r + i * 8) * 256 + c];
#pragma unroll
    for (int i = 0; i < 8; ++i) rb[i] = Wih[nrow[i] * 256 + c];

    for (int kt = 0; kt < 16; ++kt) {
#pragma unroll
        for (int i = 0; i < 4; ++i) sm->lstm.As[r + i * 8][c] = ra[i];
#pragma unroll
        for (int i = 0; i < 8; ++i) sm->lstm.Bs[r + i * 8][c] = rb[i];
        __syncthreads();
        if (kt < 15) {
            int kg = (kt + 1) * 32;
            const float* Ap = (kg < 256) ? query : state1;
            const float* Bp = (kg < 256) ? Wih : Whh;
            int kof = kg & 255;
#pragma unroll
            for (int i = 0; i < 4; ++i) ra[i] = Ap[(m0 + r + i * 8) * 256 + kof + c];
#pragma unroll
            for (int i = 0; i < 8; ++i) rb[i] = Bp[nrow[i] * 256 + kof + c];
        }
#pragma unroll
        for (int kk = 0; kk < 32; ++kk) {
            float a0 = sm->lstm.As[ty * 2][kk];
            float a1 = sm->lstm.As[ty * 2 + 1][kk];
            float b[4];
#pragma unroll
            for (int g = 0; g < 4; ++g) b[g] = sm->lstm.Bs[g * 16 + tx][kk];
#pragma unroll
            for (int g = 0; g < 4; ++g) {
                acc[0][g] = fmaf(a0, b[g], acc[0][g]);
                acc[1][g] = fmaf(a1, b[g], acc[1][g]);
            }
        }
        __syncthreads();
    }
    int col = colbase + tx;
#pragma unroll
    for (int i = 0; i < 2; ++i) {
        int m = m0 + ty * 2 + i;
        int idx = m * 256 + col;
        float gi = acc[i][0] + bih[col]       + bhh[col];
        float gf = acc[i][1] + bih[256 + col] + bhh[256 + col];
        float gg = acc[i][2] + bih[512 + col] + bhh[512 + col];
        float go = acc[i][3] + bih[768 + col] + bhh[768 + col];
        float cc = sigmoid_f(gf) * state2[idx] + sigmoid_f(gi) * tanh_fast(gg);
        float hh = sigmoid_f(go) * tanh_fast(cc);
        out[idx] = hh;
        out[B_DIM * H_DIM + idx] = cc;
    }
}

// Generic 512x256x256 GEMM, tile 16m x 32n, 256 tiles.
// isQ: B[k][n] = nnQ[n>>5][k][n&31], scaled; else B[k][n] = O[k*256+n].
__device__ void stage_gem(const float* __restrict__ A,
                          const float* __restrict__ Bm,
                          float* __restrict__ C, bool isQ, SmemU* sm) {
    int tile = blockIdx.x;
    if (tile >= 256) return;
    int m0 = (tile >> 3) * 16;
    int n0 = (tile & 7) * 32;
    int tid = threadIdx.x;
    int r = tid >> 5, c = tid & 31;
    int ty = tid >> 5, tx = tid & 31;       // m pair = ty, n col = tx
    float acc[2] = {};
    const float* Bbase = isQ ? (Bm + (n0 >> 5) * (H_DIM * HD)) : (Bm + n0);
    int bstride = isQ ? HD : H_DIM;
    float ra[2], rb[4];
#pragma unroll
    for (int i = 0; i < 2; ++i) ra[i] = A[(m0 + r + i * 8) * 256 + c];
#pragma unroll
    for (int i = 0; i < 4; ++i) rb[i] = Bbase[(r + i * 8) * bstride + c];
    for (int kt = 0; kt < 8; ++kt) {
#pragma unroll
        for (int i = 0; i < 2; ++i) sm->gem.As[r + i * 8][c] = ra[i];
#pragma unroll
        for (int i = 0; i < 4; ++i) sm->gem.Bs[r + i * 8][c] = rb[i];
        __syncthreads();
        if (kt < 7) {
            int k0 = (kt + 1) * 32;
#pragma unroll
            for (int i = 0; i < 2; ++i) ra[i] = A[(m0 + r + i * 8) * 256 + k0 + c];
#pragma unroll
            for (int i = 0; i < 4; ++i) rb[i] = Bbase[(k0 + r + i * 8) * bstride + c];
        }
#pragma unroll
        for (int kk = 0; kk < 32; ++kk) {
            float b = sm->gem.Bs[kk][tx];
            acc[0] = fmaf(sm->gem.As[ty * 2][kk], b, acc[0]);
            acc[1] = fmaf(sm->gem.As[ty * 2 + 1][kk], b, acc[1]);
        }
        __syncthreads();
    }
    float scale = isQ ? 0.17677669529663687f : 1.0f;
    C[(m0 + ty * 2) * 256 + n0 + tx]     = acc[0] * scale;
    C[(m0 + ty * 2 + 1) * 256 + n0 + tx] = acc[1] * scale;
}

__device__ void stage_attn(const float* __restrict__ Kt,
                           const float* __restrict__ Vt,
                           const void* __restrict__ mask, SmemU* sm) {
    int tid = threadIdx.x;
    int w = tid >> 5, l = tid & 31;
    int mode = load_maskmode();
    for (int job = blockIdx.x; job < NP * HEADS; job += GRID) {
        int p = job & 63, a = job >> 6;
        __syncthreads();
        sm->attn.Qs[tid] = g_Qg[(p * NR + w) * H_DIM + a * HD + l];
        __syncthreads();

        // S pass: thread-per-k
        const float* Kbase = Kt + ((size_t)(a * NP + p)) * NK * HD;
        for (int k = tid; k < NK; k += 256) {
            const float4* kr = (const float4*)(Kbase + k * HD);
            float acc[NR] = {};
#pragma unroll
            for (int d4 = 0; d4 < 8; ++d4) {
                float4 kv = kr[d4];
#pragma unroll
                for (int q = 0; q < NR; ++q) {
                    float4 qv = *(const float4*)(sm->attn.Qs + q * HD + d4 * 4);
                    acc[q] = fmaf(qv.x, kv.x,
                             fmaf(qv.y, kv.y,
                             fmaf(qv.z, kv.z,
                             fmaf(qv.w, kv.w, acc[q]))));
                }
            }
            *(float4*)&sm->attn.Ss[k * 8]     = make_float4(acc[0], acc[1], acc[2], acc[3]);
            *(float4*)&sm->attn.Ss[k * 8 + 4] = make_float4(acc[4], acc[5], acc[6], acc[7]);
        }
        __syncthreads();

        // softmax per q (warp w = q), mask applied here
        {
            int q = w;
            int mbase = p * (NR * NK) + q * NK;
            float mx = NEG_INF;
            for (int k = l; k < NK; k += 32) {
                float v = sm->attn.Ss[k * 8 + q];
                if (get_mask(mask, mbase + k, mode)) { v = NEG_INF; sm->attn.Ss[k * 8 + q] = v; }
                mx = fmaxf(mx, v);
            }
#pragma unroll
            for (int o = 16; o; o >>= 1) mx = fmaxf(mx, __shfl_xor_sync(0xffffffffu, mx, o));
            float s = 0.f;
            for (int k = l; k < NK; k += 32) {
                float e = __expf(sm->attn.Ss[k * 8 + q] - mx);
                sm->attn.Ss[k * 8 + q] = e;
                s += e;
            }
#pragma unroll
            for (int o = 16; o; o >>= 1) s += __shfl_xor_sync(0xffffffffu, s, o);
            if (l == 0) sm->attn.sinv[q] = 1.f / s;
        }
        __syncthreads();

        // x = P @ V : warp owns a k-chunk for all q
        {
            int k0 = (NK * w) / 8, k1 = (NK * (w + 1)) / 8;
            float acc[NR] = {};
            const float* Vb = Vt + ((size_t)(a * NP + p)) * NK * HD + l;
            for (int k = k0; k < k1; ++k) {
                float v = Vb[k * HD];
                float4 p0 = *(const float4*)&sm->attn.Ss[k * 8];
                float4 p1 = *(const float4*)&sm->attn.Ss[k * 8 + 4];
                acc[0] = fmaf(p0.x, v, acc[0]);
                acc[1] = fmaf(p0.y, v, acc[1]);
                acc[2] = fmaf(p0.z, v, acc[2]);
                acc[3] = fmaf(p0.w, v, acc[3]);
                acc[4] = fmaf(p1.x, v, acc[4]);
                acc[5] = fmaf(p1.y, v, acc[5]);
                acc[6] = fmaf(p1.z, v, acc[6]);
                acc[7] = fmaf(p1.w, v, acc[7]);
            }
#pragma unroll
            for (int q = 0; q < NR; ++q) sm->attn.xp[w][q][l] = acc[q];
        }
        __syncthreads();
        {
            float s = 0.f;
#pragma unroll
            for (int u = 0; u < 8; ++u) s += sm->attn.xp[u][w][l];
            g_xg[(p * NR + w) * H_DIM + a * HD + l] = s * sm->attn.sinv[w];
        }
    }
}

__device__ void stage_logits(const float* __restrict__ X,
                             const float* __restrict__ varfeat,
                             const void* __restrict__ mask,
                             const float* __restrict__ nnA,
                             const float* __restrict__ nnB,
                             const float* __restrict__ nnW, SmemU* sm) {
    int tid = threadIdx.x, w = tid >> 5, l = tid & 31;
    int mode = load_maskmode();
    float Wv[8];
#pragma unroll
    for (int j = 0; j < 8; ++j) Wv[j] = nnW[l + 32 * j];
    for (int job = blockIdx.x; job < NP * 10; job += GRID) {
        int p = job / 10;
        int kbase = (job % 10) * KCH;
        __syncthreads();
        for (int e = tid; e < NR * H_DIM; e += 256) {
            sm->lg.qs[e] = g_qm[p * NR * H_DIM + e];
            sm->lg.As[e] = nnA[e];
        }
        sm->lg.B[tid] = nnB[tid];
        for (int e = tid; e < VD * KCH; e += 256) {
            int v = e / KCH, kk = e % KCH;
            sm->lg.vfs[v][kk] = varfeat[(p * VD + v) * NK + kbase + kk];
        }
        __syncthreads();

        for (int k = kbase + w; k < kbase + KCH; k += 8) {
            int kk = k - kbase;
            const float* Xr = X + ((size_t)p * NK + k) * H_DIM;
            float base[8];
#pragma unroll
            for (int j = 0; j < 8; ++j) base[j] = Xr[l + 32 * j] + sm->lg.B[l + 32 * j];
#pragma unroll
            for (int v = 0; v < VD; ++v) {
                float f = sm->lg.vfs[v][kk];
#pragma unroll
                for (int j = 0; j < 8; ++j)
                    base[j] = fmaf(f, sm->lg.As[v * H_DIM + l + 32 * j], base[j]);
            }
            int mb = p * (NR * NK) + k;
#pragma unroll
            for (int q = 0; q < NR; ++q) {
                float outv;
                if (get_mask(mask, mb + q * NK, mode)) {
                    outv = NEG_INF;
                } else {
                    float s = 0.f;
#pragma unroll
                    for (int j = 0; j < 8; ++j)
                        s = fmaf(tanh_approx(base[j] + sm->lg.qs[q * H_DIM + l + 32 * j]), Wv[j], s);
#pragma unroll
                    for (int o = 16; o; o >>= 1) s += __shfl_xor_sync(0xffffffffu, s, o);
                    outv = 10.f * tanh_fast(s);
                }
                if (l == 0) g_L[(p * NR + q) * NK + k] = outv;
            }
        }
    }
}

__device__ void stage_choose(float* __restrict__ out) {
    int w = threadIdx.x >> 5, l = threadIdx.x & 31;
    int r = blockIdx.x * 8 + w;
    if (r >= B_DIM) return;
    const float* Lr = g_L + r * NK;
    float best = NEG_INF;
    for (int k = l; k < NK; k += 32) best = fmaxf(best, Lr[k]);
#pragma unroll
    for (int o = 16; o; o >>= 1) best = fmaxf(best, __shfl_xor_sync(0xffffffffu, best, o));
    float s = 0.f;
    for (int k = l; k < NK; k += 32) {
        float v = Lr[k];
        if (v > NEG_INF) s += __expf(v - best);
    }
#pragma unroll
    for (int o = 16; o; o >>= 1) s += __shfl_xor_sync(0xffffffffu, s, o);
    if (l == 0) out[2 * B_DIM * H_DIM + r] = -logf(s);
}

// =========================== persistent kernel ===========================
__global__ __launch_bounds__(TPB, 2)
void decode_persistent(const float* __restrict__ X,
                       const float* __restrict__ Kt,
                       const float* __restrict__ Vt,
                       const float* __restrict__ query,
                       const float* __restrict__ state1,
                       const float* __restrict__ state2,
                       const float* __restrict__ varfeat,
                       const void*  __restrict__ mask,
                       const float* __restrict__ nnQ,
                       const float* __restrict__ nnO,
                       const float* __restrict__ nnA,
                       const float* __restrict__ nnB,
                       const float* __restrict__ nnW,
                       const float* __restrict__ Wih,
                       const float* __restrict__ Whh,
                       const float* __restrict__ bih,
                       const float* __restrict__ bhh,
                       float* __restrict__ out) {
    __shared__ SmemU sm;
    stage_probe((const unsigned int*)mask);
    stage_lstm(query, state1, Wih, Whh, bih, bhh, state2, out, &sm);
    gsync();                                    // h,c + mask flags visible
    stage_gem(out, nnQ, g_Qg, true, &sm);       // Q projection (reads h)
    gsync();
    stage_attn(Kt, Vt, mask, &sm);              // -> g_xg
    gsync();
    stage_gem(g_xg, nnO, g_qm, false, &sm);     // qm
    gsync();
    stage_logits(X, varfeat, mask, nnA, nnB, nnW, &sm);  // -> g_L
    gsync();
    stage_choose(out);
}

// ---------------- launch ----------------
extern "C" void kernel_launch(void* const* d_in, const int* in_sizes, int n_in,
                              void* d_out, int out_size) {
    const float* X       = (const float*)d_in[0];
    const float* Kt      = (const float*)d_in[1];
    const float* Vt      = (const float*)d_in[2];
    const float* query   = (const float*)d_in[3];
    const float* state1  = (const float*)d_in[4];
    const float* state2  = (const float*)d_in[5];
    const float* varfeat = (const float*)d_in[6];
    const void*  mask    = (const void*) d_in[7];
    const float* nnQ     = (const float*)d_in[8];
    const float* nnO     = (const float*)d_in[9];
    const float* nnA     = (const float*)d_in[10];
    const float* nnB     = (const float*)d_in[11];
    const float* nnW     = (const float*)d_in[12];
    const float* Wih     = (const float*)d_in[13];
    const float* Whh     = (const float*)d_in[14];
    const float* bih     = (const float*)d_in[15];
    const float* bhh     = (const float*)d_in[16];
    float* out = (float*)d_out;

    decode_persistent<<<GRID, TPB>>>(X, Kt, Vt, query, state1, state2, varfeat,
                                     mask, nnQ, nnO, nnA, nnB, nnW,
                                     Wih, Whh, bih, bhh, out);
}